// round 3
// baseline (speedup 1.0000x reference)
#include <cuda_runtime.h>
#include <float.h>
#include <math.h>

#define N_PROT 50000
#define N_SUB  2000
#define D      256     // D_PROT == D_SUB
#define DP     128     // D_PROJ
#define KERN   16
#define N_INT  64
#define NW     (N_PROT - KERN + 1)   // 49985

#define NB_PROT 6250      // 6250*8 = 50000 rows
#define NB_SUB  250       // 250*8  = 2000 rows
#define NB_K1   (NB_PROT + NB_SUB + 1)
#define NB_WIN  196       // 196*256 = 50176 >= NW

// -------- device scratch (no allocations allowed) --------
__device__ float d_g[N_PROT];     // g minus constant (shift-invariant uses only)
__device__ float d_s[N_PROT];     // rowsum(prot_proj) minus constant
__device__ float d_v[D];          // Wp @ w1
__device__ float d_u[D];          // Wp @ ones
__device__ float d_reaction[DP];
__device__ float d_blkVal[NB_WIN];
__device__ int   d_blkIdx[NB_WIN];
__device__ int   d_count;         // zero-initialized; reset after each use

// ============================================================
// k0: v = Wp @ w1, u = Wp @ ones  (warp-per-row, coalesced)
//     reaction = colsum(sub_node[int_index]) @ Ws + 64*bs
// ============================================================
__global__ void k0_prep(const float* __restrict__ sub_node,
                        const int*   __restrict__ int_index,
                        const float* __restrict__ Wp,
                        const float* __restrict__ Ws,
                        const float* __restrict__ bs,
                        const float* __restrict__ wa)
{
    __shared__ float  ssum[D];
    __shared__ float4 swa4[DP / 4];     // wa[0:128] as float4
    int t    = threadIdx.x;   // 256 threads
    int lane = t & 31;
    int warp = t >> 5;

    if (t < DP / 4) swa4[t] = ((const float4*)wa)[t];

    // column sum of the 64 selected sub rows (coalesced)
    {
        float acc = 0.f;
        #pragma unroll 8
        for (int m = 0; m < N_INT; m++)
            acc += sub_node[(size_t)int_index[m] * D + t];
        ssum[t] = acc;
    }
    __syncthreads();

    // v,u: one warp per row of Wp; lane loads float4 (coalesced)
    for (int it = 0; it < D / 8; it++) {
        int row = it * 8 + warp;
        float4 w = ((const float4*)(Wp + (size_t)row * DP))[lane];
        float4 a = swa4[lane];
        float vv = w.x*a.x + w.y*a.y + w.z*a.z + w.w*a.w;
        float uu = w.x + w.y + w.z + w.w;
        #pragma unroll
        for (int o = 16; o > 0; o >>= 1) {
            vv += __shfl_xor_sync(0xffffffffu, vv, o);
            uu += __shfl_xor_sync(0xffffffffu, uu, o);
        }
        if (lane == 0) { d_v[row] = vv; d_u[row] = uu; }
    }

    // reaction (coalesced over t)
    if (t < DP) {
        float r = 0.f;
        #pragma unroll 16
        for (int j = 0; j < D; j++)
            r += ssum[j] * Ws[j * DP + t];
        d_reaction[t] = r + (float)N_INT * bs[t];
    }
}

// ============================================================
// k1: fused prot copy + g/s matvecs, sub copy, index tail
// ============================================================
__global__ void k1_main(const float* __restrict__ prot,
                        const float* __restrict__ subn,
                        const int*   __restrict__ idx,
                        float* __restrict__ out)
{
    int b    = blockIdx.x;
    int t    = threadIdx.x;
    int warp = t >> 5;
    int lane = t & 31;

    if (b < NB_PROT) {
        int row = b * 8 + warp;
        const float4* src = (const float4*)(prot + (size_t)row * D);
        float4*       dst = (float4*)(out + (size_t)row * D);
        const float4* v4  = (const float4*)d_v;
        const float4* u4  = (const float4*)d_u;

        float4 a = src[lane];
        float4 c = src[lane + 32];
        dst[lane]      = a;
        dst[lane + 32] = c;

        float4 va = v4[lane], vc = v4[lane + 32];
        float4 ua = u4[lane], uc = u4[lane + 32];

        float gv = a.x*va.x + a.y*va.y + a.z*va.z + a.w*va.w
                 + c.x*vc.x + c.y*vc.y + c.z*vc.z + c.w*vc.w;
        float sv = a.x*ua.x + a.y*ua.y + a.z*ua.z + a.w*ua.w
                 + c.x*uc.x + c.y*uc.y + c.z*uc.z + c.w*uc.w;

        #pragma unroll
        for (int o = 16; o > 0; o >>= 1) {
            gv += __shfl_down_sync(0xffffffffu, gv, o);
            sv += __shfl_down_sync(0xffffffffu, sv, o);
        }
        if (lane == 0) {
            d_g[row] = gv;
            d_s[row] = sv;
        }
    } else if (b < NB_PROT + NB_SUB) {
        int row = (b - NB_PROT) * 8 + warp;
        const float4* src = (const float4*)(subn + (size_t)row * D);
        float4*       dst = (float4*)(out + (size_t)(N_PROT + row) * D);
        dst[lane]      = src[lane];
        dst[lane + 32] = src[lane + 32];
    } else {
        if (t < N_INT)
            out[(size_t)(N_PROT + N_SUB) * D + t] = (float)idx[t];
    }
}

// ============================================================
// k2: per-window softmax score + block argmax; LAST block also
//     does the full finalize (ticket pattern).
// ============================================================
__global__ void __launch_bounds__(256)
k2_window_final(const float* __restrict__ prot,
                const float* __restrict__ subn,
                const int*   __restrict__ idx,
                const float* __restrict__ Wp,
                const float* __restrict__ bp,
                const float* __restrict__ sub_out,
                const float* __restrict__ prot_out,
                float* __restrict__ out)
{
    __shared__ float sg[256 + KERN];
    __shared__ float ss[256 + KERN];
    __shared__ float bval[256];
    __shared__ int   bidx[256];
    __shared__ int   s_last;

    int b    = blockIdx.x;
    int t    = threadIdx.x;
    int base = b * 256;

    for (int i = t; i < 256 + KERN - 1; i += 256) {
        int gi = base + i;
        sg[i] = (gi < N_PROT) ? d_g[gi] : -FLT_MAX;
        ss[i] = (gi < N_PROT) ? d_s[gi] : 0.f;
    }
    __syncthreads();

    int   w = base + t;
    float A = -FLT_MAX;
    if (w < NW) {
        float m = sg[t];
        #pragma unroll
        for (int k = 1; k < KERN; k++) m = fmaxf(m, sg[t + k]);
        float wsum = 0.f, asum = 0.f;
        #pragma unroll
        for (int k = 0; k < KERN; k++) {
            float e = expf(sg[t + k] - m);
            wsum += e;
            asum += e * ss[t + k];
        }
        A = asum / wsum;
    }
    bval[t] = A;
    bidx[t] = w;
    __syncthreads();

    for (int off = 128; off > 0; off >>= 1) {
        if (t < off) {
            float ov = bval[t + off];
            int   oi = bidx[t + off];
            if (ov > bval[t] || (ov == bval[t] && oi < bidx[t])) {
                bval[t] = ov;
                bidx[t] = oi;
            }
        }
        __syncthreads();
    }
    if (t == 0) {
        d_blkVal[b] = bval[0];
        d_blkIdx[b] = bidx[0];
        __threadfence();
        int ticket = atomicAdd(&d_count, 1);
        s_last = (ticket == NB_WIN - 1);
    }
    __syncthreads();
    if (!s_last) return;

    // ================= finalize (last block only) =================
    __shared__ float attn[KERN];
    __shared__ float wrow[D];         // attn-weighted prot row
    __shared__ float ts[DP];          // top_score
    __shared__ float dprot[D];
    __shared__ float dsub[D];
    __shared__ int   s_top;

    // reduce 196 candidates -> top
    if (t < NB_WIN) { bval[t] = d_blkVal[t]; bidx[t] = d_blkIdx[t]; }
    else            { bval[t] = -FLT_MAX;    bidx[t] = 0x7fffffff; }
    __syncthreads();
    for (int off = 128; off > 0; off >>= 1) {
        if (t < off) {
            float ov = bval[t + off];
            int   oi = bidx[t + off];
            if (ov > bval[t] || (ov == bval[t] && oi < bidx[t])) {
                bval[t] = ov;
                bidx[t] = oi;
            }
        }
        __syncthreads();
    }
    if (t == 0) { s_top = bidx[0]; d_count = 0; }   // reset for graph replay
    __syncthreads();
    int top = s_top;

    // attn (one warp)
    if (t < 32) {
        float gk = (t < KERN) ? d_g[top + t] : -FLT_MAX;
        float m = gk;
        #pragma unroll
        for (int o = 16; o > 0; o >>= 1)
            m = fmaxf(m, __shfl_xor_sync(0xffffffffu, m, o));
        float e = (t < KERN) ? expf(gk - m) : 0.f;
        float sum = e;
        #pragma unroll
        for (int o = 16; o > 0; o >>= 1)
            sum += __shfl_xor_sync(0xffffffffu, sum, o);
        if (t < KERN) attn[t] = e / sum;
    }
    __syncthreads();

    // weighted prot row: wrow[j] = sum_k attn[k] * prot[top+k][j]
    {
        float acc = 0.f;
        #pragma unroll
        for (int k = 0; k < KERN; k++)
            acc += attn[k] * prot[(size_t)(top + k) * D + t];
        wrow[t] = acc;
    }
    __syncthreads();

    // top_score[d] = reaction[d] + bp[d] + wrow @ Wp[:,d]
    if (t < DP) {
        float acc = d_reaction[t] + bp[t];
        #pragma unroll 16
        for (int j = 0; j < D; j++)
            acc += wrow[j] * Wp[j * DP + t];
        ts[t] = acc;
    }
    __syncthreads();

    // deltas: prot_out / sub_out are (128, 256) row-major
    {
        float dp_ = 0.f, ds_ = 0.f;
        #pragma unroll 16
        for (int d = 0; d < DP; d++) {
            float s = ts[d];
            dp_ += s * prot_out[d * D + t];
            ds_ += s * sub_out[d * D + t];
        }
        dprot[t] = dp_;
        dsub[t]  = ds_;
    }
    __syncthreads();

    // patch 16 prot rows (out already holds the copy)
    #pragma unroll
    for (int k = 0; k < KERN; k++)
        out[(size_t)(top + k) * D + t] += dprot[t];

    // patch 64 sub rows (set semantics; duplicates write identical value)
    for (int m = 0; m < N_INT; m++) {
        int r = idx[m];
        out[(size_t)(N_PROT + r) * D + t] = subn[(size_t)r * D + t] + dsub[t];
    }
}

// ============================================================
extern "C" void kernel_launch(void* const* d_in, const int* in_sizes, int n_in,
                              void* d_out, int out_size)
{
    const float* prot_node = (const float*)d_in[0];
    const float* sub_node  = (const float*)d_in[1];
    const int*   int_index = (const int*)  d_in[2];
    const float* Wp        = (const float*)d_in[3];
    const float* bp        = (const float*)d_in[4];
    const float* Ws        = (const float*)d_in[5];
    const float* bs        = (const float*)d_in[6];
    const float* wa        = (const float*)d_in[7];
    const float* sub_out   = (const float*)d_in[9];
    const float* prot_out  = (const float*)d_in[10];
    float*       out       = (float*)d_out;

    k0_prep<<<1, 256>>>(sub_node, int_index, Wp, Ws, bs, wa);
    k1_main<<<NB_K1, 256>>>(prot_node, sub_node, int_index, out);
    k2_window_final<<<NB_WIN, 256>>>(prot_node, sub_node, int_index,
                                     Wp, bp, sub_out, prot_out, out);
}

// round 4
// speedup vs baseline: 1.5050x; 1.5050x over previous
#include <cuda_runtime.h>
#include <float.h>
#include <math.h>

#define N_PROT 50000
#define N_SUB  2000
#define D      256     // D_PROT == D_SUB
#define DP     128     // D_PROJ
#define KERN   16
#define N_INT  64
#define NW     (N_PROT - KERN + 1)   // 49985

#define NB_PROT 6250      // 6250*8 = 50000 rows
#define NB_SUB  250       // 250*8  = 2000 rows
#define NB_K1   (NB_PROT + NB_SUB + 1)
#define NB_WIN  196       // 196*256 = 50176 >= NW
#define NB_K0   33        // block 0: reaction; blocks 1..32: v/u (8 rows each)

// -------- device scratch (no allocations allowed) --------
__device__ float d_g[N_PROT];     // g minus constant (shift-invariant uses only)
__device__ float d_s[N_PROT];     // rowsum(prot_proj) minus constant
__device__ float d_v[D];          // Wp @ w1
__device__ float d_u[D];          // Wp @ ones
__device__ float d_reaction[DP];
__device__ float d_blkVal[NB_WIN];
__device__ int   d_blkIdx[NB_WIN];
__device__ int   d_count;         // zero-initialized; reset by finalize

// ============================================================
// k0 (33 blocks):
//   block 0   : reaction = colsum(sub_node[int_index]) @ Ws + 64*bs
//   blocks 1..32: v = Wp @ w1, u = Wp @ ones  (warp-per-row, ONE iter)
// ============================================================
__global__ void k0_prep(const float* __restrict__ sub_node,
                        const int*   __restrict__ int_index,
                        const float* __restrict__ Wp,
                        const float* __restrict__ Ws,
                        const float* __restrict__ bs,
                        const float* __restrict__ wa)
{
    int b    = blockIdx.x;
    int t    = threadIdx.x;   // 256 threads
    int lane = t & 31;
    int warp = t >> 5;

    if (b == 0) {
        __shared__ float ssum[D];
        __shared__ float part[DP];   // high-half partials

        // column sum of the 64 selected sub rows (coalesced, idx broadcast)
        float acc = 0.f;
        #pragma unroll 16
        for (int m = 0; m < N_INT; m++)
            acc += sub_node[(size_t)int_index[m] * D + t];
        ssum[t] = acc;
        __syncthreads();

        // reaction: 128 outputs, 2 threads each (j-halves), deep unroll
        {
            int c    = t & (DP - 1);
            int half = t >> 7;             // 0 or 1
            int j0   = half * (D / 2);
            float r = 0.f;
            #pragma unroll 32
            for (int j = 0; j < D / 2; j++)
                r += ssum[j0 + j] * Ws[(j0 + j) * DP + c];
            if (half) part[c] = r;
            __syncthreads();
            if (!half)
                d_reaction[c] = r + part[c] + (float)N_INT * bs[c];
        }
    } else {
        // one warp per Wp row, single iteration (short shuffle chain)
        int row = (b - 1) * 8 + warp;
        float4 w = ((const float4*)(Wp + (size_t)row * DP))[lane];
        float4 a = ((const float4*)wa)[lane];
        float vv = w.x*a.x + w.y*a.y + w.z*a.z + w.w*a.w;
        float uu = w.x + w.y + w.z + w.w;
        #pragma unroll
        for (int o = 16; o > 0; o >>= 1) {
            vv += __shfl_xor_sync(0xffffffffu, vv, o);
            uu += __shfl_xor_sync(0xffffffffu, uu, o);
        }
        if (lane == 0) { d_v[row] = vv; d_u[row] = uu; }
    }
}

// ============================================================
// k1: fused prot copy + g/s matvecs, sub copy, index tail
// ============================================================
__global__ void k1_main(const float* __restrict__ prot,
                        const float* __restrict__ subn,
                        const int*   __restrict__ idx,
                        float* __restrict__ out)
{
    int b    = blockIdx.x;
    int t    = threadIdx.x;
    int warp = t >> 5;
    int lane = t & 31;

    if (b < NB_PROT) {
        int row = b * 8 + warp;
        const float4* src = (const float4*)(prot + (size_t)row * D);
        float4*       dst = (float4*)(out + (size_t)row * D);
        const float4* v4  = (const float4*)d_v;
        const float4* u4  = (const float4*)d_u;

        float4 a = src[lane];
        float4 c = src[lane + 32];
        dst[lane]      = a;
        dst[lane + 32] = c;

        float4 va = v4[lane], vc = v4[lane + 32];
        float4 ua = u4[lane], uc = u4[lane + 32];

        float gv = a.x*va.x + a.y*va.y + a.z*va.z + a.w*va.w
                 + c.x*vc.x + c.y*vc.y + c.z*vc.z + c.w*vc.w;
        float sv = a.x*ua.x + a.y*ua.y + a.z*ua.z + a.w*ua.w
                 + c.x*uc.x + c.y*uc.y + c.z*uc.z + c.w*uc.w;

        #pragma unroll
        for (int o = 16; o > 0; o >>= 1) {
            gv += __shfl_down_sync(0xffffffffu, gv, o);
            sv += __shfl_down_sync(0xffffffffu, sv, o);
        }
        if (lane == 0) {
            d_g[row] = gv;
            d_s[row] = sv;
        }
    } else if (b < NB_PROT + NB_SUB) {
        int row = (b - NB_PROT) * 8 + warp;
        const float4* src = (const float4*)(subn + (size_t)row * D);
        float4*       dst = (float4*)(out + (size_t)(N_PROT + row) * D);
        dst[lane]      = src[lane];
        dst[lane + 32] = src[lane + 32];
    } else {
        if (t < N_INT)
            out[(size_t)(N_PROT + N_SUB) * D + t] = (float)idx[t];
    }
}

// ============================================================
// k2: per-window softmax score + block argmax; LAST block also
//     does the full finalize (ticket pattern).
// ============================================================
__global__ void __launch_bounds__(256)
k2_window_final(const float* __restrict__ prot,
                const float* __restrict__ subn,
                const int*   __restrict__ idx,
                const float* __restrict__ Wp,
                const float* __restrict__ bp,
                const float* __restrict__ sub_out,
                const float* __restrict__ prot_out,
                float* __restrict__ out)
{
    __shared__ float sg[256 + KERN];
    __shared__ float ss[256 + KERN];
    __shared__ float bval[256];
    __shared__ int   bidx[256];
    __shared__ int   s_last;

    int b    = blockIdx.x;
    int t    = threadIdx.x;
    int base = b * 256;

    for (int i = t; i < 256 + KERN - 1; i += 256) {
        int gi = base + i;
        sg[i] = (gi < N_PROT) ? d_g[gi] : -FLT_MAX;
        ss[i] = (gi < N_PROT) ? d_s[gi] : 0.f;
    }
    __syncthreads();

    int   w = base + t;
    float A = -FLT_MAX;
    if (w < NW) {
        float m = sg[t];
        #pragma unroll
        for (int k = 1; k < KERN; k++) m = fmaxf(m, sg[t + k]);
        float wsum = 0.f, asum = 0.f;
        #pragma unroll
        for (int k = 0; k < KERN; k++) {
            float e = expf(sg[t + k] - m);
            wsum += e;
            asum += e * ss[t + k];
        }
        A = asum / wsum;
    }
    bval[t] = A;
    bidx[t] = w;
    __syncthreads();

    for (int off = 128; off > 0; off >>= 1) {
        if (t < off) {
            float ov = bval[t + off];
            int   oi = bidx[t + off];
            if (ov > bval[t] || (ov == bval[t] && oi < bidx[t])) {
                bval[t] = ov;
                bidx[t] = oi;
            }
        }
        __syncthreads();
    }
    if (t == 0) {
        d_blkVal[b] = bval[0];
        d_blkIdx[b] = bidx[0];
        __threadfence();
        int ticket = atomicAdd(&d_count, 1);
        s_last = (ticket == NB_WIN - 1);
    }
    __syncthreads();
    if (!s_last) return;

    // ================= finalize (last block only) =================
    __shared__ float attn[KERN];
    __shared__ float wrow[D];         // attn-weighted prot row
    __shared__ float ts[DP];          // top_score
    __shared__ float tpart[DP];       // ts high-half partials
    __shared__ float dprot[D];
    __shared__ float dsub[D];
    __shared__ int   s_top;

    // reduce 196 candidates -> top
    if (t < NB_WIN) { bval[t] = d_blkVal[t]; bidx[t] = d_blkIdx[t]; }
    else            { bval[t] = -FLT_MAX;    bidx[t] = 0x7fffffff; }
    __syncthreads();
    for (int off = 128; off > 0; off >>= 1) {
        if (t < off) {
            float ov = bval[t + off];
            int   oi = bidx[t + off];
            if (ov > bval[t] || (ov == bval[t] && oi < bidx[t])) {
                bval[t] = ov;
                bidx[t] = oi;
            }
        }
        __syncthreads();
    }
    if (t == 0) { s_top = bidx[0]; d_count = 0; }   // reset for graph replay
    __syncthreads();
    int top = s_top;

    // attn (one warp)
    if (t < 32) {
        float gk = (t < KERN) ? d_g[top + t] : -FLT_MAX;
        float m = gk;
        #pragma unroll
        for (int o = 16; o > 0; o >>= 1)
            m = fmaxf(m, __shfl_xor_sync(0xffffffffu, m, o));
        float e = (t < KERN) ? expf(gk - m) : 0.f;
        float sum = e;
        #pragma unroll
        for (int o = 16; o > 0; o >>= 1)
            sum += __shfl_xor_sync(0xffffffffu, sum, o);
        if (t < KERN) attn[t] = e / sum;
    }
    __syncthreads();

    // weighted prot row: wrow[j] = sum_k attn[k] * prot[top+k][j]
    {
        float acc = 0.f;
        #pragma unroll
        for (int k = 0; k < KERN; k++)
            acc += attn[k] * prot[(size_t)(top + k) * D + t];
        wrow[t] = acc;
    }
    __syncthreads();

    // top_score[d] = reaction[d] + bp[d] + wrow @ Wp[:,d]
    // 128 outputs, 2 threads each (j-halves), deep unroll
    {
        int c    = t & (DP - 1);
        int half = t >> 7;
        int j0   = half * (D / 2);
        float acc = 0.f;
        #pragma unroll 32
        for (int j = 0; j < D / 2; j++)
            acc += wrow[j0 + j] * Wp[(j0 + j) * DP + c];
        if (half) tpart[c] = acc;
        __syncthreads();
        if (!half) ts[c] = acc + tpart[c] + d_reaction[c] + bp[c];
    }
    __syncthreads();

    // deltas: prot_out / sub_out are (128, 256) row-major
    {
        float dp_ = 0.f, ds_ = 0.f;
        #pragma unroll 32
        for (int d = 0; d < DP; d++) {
            float s = ts[d];
            dp_ += s * prot_out[d * D + t];
            ds_ += s * sub_out[d * D + t];
        }
        dprot[t] = dp_;
        dsub[t]  = ds_;
    }
    __syncthreads();

    // patch 16 prot rows (out already holds the copy)
    #pragma unroll
    for (int k = 0; k < KERN; k++)
        out[(size_t)(top + k) * D + t] += dprot[t];

    // patch 64 sub rows (set semantics; duplicates write identical value)
    #pragma unroll 4
    for (int m = 0; m < N_INT; m++) {
        int r = idx[m];
        out[(size_t)(N_PROT + r) * D + t] = subn[(size_t)r * D + t] + dsub[t];
    }
}

// ============================================================
extern "C" void kernel_launch(void* const* d_in, const int* in_sizes, int n_in,
                              void* d_out, int out_size)
{
    const float* prot_node = (const float*)d_in[0];
    const float* sub_node  = (const float*)d_in[1];
    const int*   int_index = (const int*)  d_in[2];
    const float* Wp        = (const float*)d_in[3];
    const float* bp        = (const float*)d_in[4];
    const float* Ws        = (const float*)d_in[5];
    const float* bs        = (const float*)d_in[6];
    const float* wa        = (const float*)d_in[7];
    const float* sub_out   = (const float*)d_in[9];
    const float* prot_out  = (const float*)d_in[10];
    float*       out       = (float*)d_out;

    k0_prep<<<NB_K0, 256>>>(sub_node, int_index, Wp, Ws, bs, wa);
    k1_main<<<NB_K1, 256>>>(prot_node, sub_node, int_index, out);
    k2_window_final<<<NB_WIN, 256>>>(prot_node, sub_node, int_index,
                                     Wp, bp, sub_out, prot_out, out);
}

// round 5
// speedup vs baseline: 2.1750x; 1.4452x over previous
#include <cuda_runtime.h>
#include <float.h>
#include <math.h>

#define N_PROT 50000
#define N_SUB  2000
#define D      256     // D_PROT == D_SUB
#define DP     128     // D_PROJ
#define KERN   16
#define N_INT  64
#define NW     (N_PROT - KERN + 1)   // 49985

#define NB_PROT 6250      // 6250*8 = 50000 rows
#define NB_SUB  250       // 250*8  = 2000 rows
#define NB_K1   (NB_PROT + NB_SUB + 1)
#define NB_WIN  196       // 196*256 = 50176 >= NW
#define N_RPART 8         // reaction partial blocks (32 j each)

// -------- device scratch (no allocations allowed) --------
__device__ float d_g[N_PROT];     // g minus constant (shift-invariant uses only)
__device__ float d_s[N_PROT];     // rowsum(prot_proj) minus constant
__device__ float d_v[D];          // Wp @ w1
__device__ float d_u[D];          // Wp @ ones
__device__ float d_react_part[N_RPART * DP];
__device__ float d_blkVal[NB_WIN];
__device__ int   d_blkIdx[NB_WIN];
__device__ int   d_count;         // k2 ticket; reset by finalize
__device__ int   d_vu_done;       // v/u producer count; reset by finalize

// ============================================================
// k1 (merged): blocks 0..31 produce v/u; blocks 32..39 produce
// reaction partials; ALL blocks then do copy + g/s matvec.
// ============================================================
__global__ void __launch_bounds__(256)
k1_main(const float* __restrict__ prot,
        const float* __restrict__ subn,
        const int*   __restrict__ idx,
        const float* __restrict__ Wp,
        const float* __restrict__ Ws,
        const float* __restrict__ wa,
        float* __restrict__ out)
{
    int b    = blockIdx.x;
    int t    = threadIdx.x;
    int warp = t >> 5;
    int lane = t & 31;

    // ---- special producer roles (first 40 blocks) ----
    if (b < 32) {
        // v/u: one warp per Wp row, single coalesced float4 load
        int row = b * 8 + warp;
        float4 w = ((const float4*)(Wp + (size_t)row * DP))[lane];
        float4 a = ((const float4*)wa)[lane];
        float vv = w.x*a.x + w.y*a.y + w.z*a.z + w.w*a.w;
        float uu = w.x + w.y + w.z + w.w;
        #pragma unroll
        for (int o = 16; o > 0; o >>= 1) {
            vv += __shfl_xor_sync(0xffffffffu, vv, o);
            uu += __shfl_xor_sync(0xffffffffu, uu, o);
        }
        if (lane == 0) { d_v[row] = vv; d_u[row] = uu; }
        __syncthreads();
        if (t == 0) { __threadfence(); atomicAdd(&d_vu_done, 1); }
    } else if (b < 32 + N_RPART) {
        // reaction partial over j-slice [j0, j0+32)
        int r  = b - 32;
        int j0 = r * 32;
        __shared__ float sacc[8][32];
        __shared__ float ssumL[32];

        int col  = t & 31;     // j within slice
        int row8 = t >> 5;     // 0..7
        float acc = 0.f;
        #pragma unroll
        for (int p = 0; p < 8; p++) {
            int m = p * 8 + row8;
            acc += subn[(size_t)idx[m] * D + j0 + col];
        }
        sacc[row8][col] = acc;
        __syncthreads();
        if (t < 32) {
            float s = 0.f;
            #pragma unroll
            for (int r8 = 0; r8 < 8; r8++) s += sacc[r8][t];
            ssumL[t] = s;
        }
        __syncthreads();
        if (t < DP) {
            float p = 0.f;
            #pragma unroll
            for (int j = 0; j < 32; j++)
                p += ssumL[j] * Ws[(j0 + j) * DP + t];
            d_react_part[r * DP + t] = p;
        }
    }

    // ---- copy + matvec phase (all blocks) ----
    if (b < NB_PROT) {
        int row = b * 8 + warp;
        const float4* src = (const float4*)(prot + (size_t)row * D);
        float4*       dst = (float4*)(out + (size_t)row * D);

        float4 a = __ldcs(src + lane);
        float4 c = __ldcs(src + lane + 32);
        __stcs(dst + lane,      a);
        __stcs(dst + lane + 32, c);

        // wait for v/u (usually already published)
        if (t == 0) {
            while (atomicAdd(&d_vu_done, 0) < 32) __nanosleep(64);
            __threadfence();
        }
        __syncthreads();

        const float4* v4 = (const float4*)d_v;
        const float4* u4 = (const float4*)d_u;
        float4 va = v4[lane], vc = v4[lane + 32];
        float4 ua = u4[lane], uc = u4[lane + 32];

        float gv = a.x*va.x + a.y*va.y + a.z*va.z + a.w*va.w
                 + c.x*vc.x + c.y*vc.y + c.z*vc.z + c.w*vc.w;
        float sv = a.x*ua.x + a.y*ua.y + a.z*ua.z + a.w*ua.w
                 + c.x*uc.x + c.y*uc.y + c.z*uc.z + c.w*uc.w;

        #pragma unroll
        for (int o = 16; o > 0; o >>= 1) {
            gv += __shfl_down_sync(0xffffffffu, gv, o);
            sv += __shfl_down_sync(0xffffffffu, sv, o);
        }
        if (lane == 0) {
            d_g[row] = gv;
            d_s[row] = sv;
        }
    } else if (b < NB_PROT + NB_SUB) {
        int row = (b - NB_PROT) * 8 + warp;
        const float4* src = (const float4*)(subn + (size_t)row * D);
        float4*       dst = (float4*)(out + (size_t)(N_PROT + row) * D);
        __stcs(dst + lane,      __ldcs(src + lane));
        __stcs(dst + lane + 32, __ldcs(src + lane + 32));
    } else {
        if (t < N_INT)
            out[(size_t)(N_PROT + N_SUB) * D + t] = (float)idx[t];
    }
}

// ============================================================
// k2: per-window softmax score + block argmax; LAST block also
//     does the full finalize (ticket pattern).
// ============================================================
__global__ void __launch_bounds__(256)
k2_window_final(const float* __restrict__ prot,
                const float* __restrict__ subn,
                const int*   __restrict__ idx,
                const float* __restrict__ Wp,
                const float* __restrict__ bp,
                const float* __restrict__ bs,
                const float* __restrict__ sub_out,
                const float* __restrict__ prot_out,
                float* __restrict__ out)
{
    __shared__ float sg[256 + KERN];
    __shared__ float ss[256 + KERN];
    __shared__ float bval[256];
    __shared__ int   bidx[256];
    __shared__ int   s_last;

    int b    = blockIdx.x;
    int t    = threadIdx.x;
    int base = b * 256;

    for (int i = t; i < 256 + KERN - 1; i += 256) {
        int gi = base + i;
        sg[i] = (gi < N_PROT) ? d_g[gi] : -FLT_MAX;
        ss[i] = (gi < N_PROT) ? d_s[gi] : 0.f;
    }
    __syncthreads();

    int   w = base + t;
    float A = -FLT_MAX;
    if (w < NW) {
        float m = sg[t];
        #pragma unroll
        for (int k = 1; k < KERN; k++) m = fmaxf(m, sg[t + k]);
        float wsum = 0.f, asum = 0.f;
        #pragma unroll
        for (int k = 0; k < KERN; k++) {
            float e = expf(sg[t + k] - m);
            wsum += e;
            asum += e * ss[t + k];
        }
        A = asum / wsum;
    }
    bval[t] = A;
    bidx[t] = w;
    __syncthreads();

    for (int off = 128; off > 0; off >>= 1) {
        if (t < off) {
            float ov = bval[t + off];
            int   oi = bidx[t + off];
            if (ov > bval[t] || (ov == bval[t] && oi < bidx[t])) {
                bval[t] = ov;
                bidx[t] = oi;
            }
        }
        __syncthreads();
    }
    if (t == 0) {
        d_blkVal[b] = bval[0];
        d_blkIdx[b] = bidx[0];
        __threadfence();
        int ticket = atomicAdd(&d_count, 1);
        s_last = (ticket == NB_WIN - 1);
    }
    __syncthreads();
    if (!s_last) return;

    // ================= finalize (last block only) =================
    __shared__ float attn[KERN];
    __shared__ float wrow[D];         // attn-weighted prot row
    __shared__ float ts[DP];          // top_score
    __shared__ float tpart[DP];       // ts high-half partials
    __shared__ float dprot[D];
    __shared__ float dsub[D];
    __shared__ int   s_top;

    // reduce 196 candidates -> top
    if (t < NB_WIN) { bval[t] = d_blkVal[t]; bidx[t] = d_blkIdx[t]; }
    else            { bval[t] = -FLT_MAX;    bidx[t] = 0x7fffffff; }
    __syncthreads();
    for (int off = 128; off > 0; off >>= 1) {
        if (t < off) {
            float ov = bval[t + off];
            int   oi = bidx[t + off];
            if (ov > bval[t] || (ov == bval[t] && oi < bidx[t])) {
                bval[t] = ov;
                bidx[t] = oi;
            }
        }
        __syncthreads();
    }
    if (t == 0) { s_top = bidx[0]; d_count = 0; d_vu_done = 0; } // reset for replay
    __syncthreads();
    int top = s_top;

    // attn (one warp)
    if (t < 32) {
        float gk = (t < KERN) ? d_g[top + t] : -FLT_MAX;
        float m = gk;
        #pragma unroll
        for (int o = 16; o > 0; o >>= 1)
            m = fmaxf(m, __shfl_xor_sync(0xffffffffu, m, o));
        float e = (t < KERN) ? expf(gk - m) : 0.f;
        float sum = e;
        #pragma unroll
        for (int o = 16; o > 0; o >>= 1)
            sum += __shfl_xor_sync(0xffffffffu, sum, o);
        if (t < KERN) attn[t] = e / sum;
    }
    __syncthreads();

    // weighted prot row: wrow[j] = sum_k attn[k] * prot[top+k][j]
    {
        float acc = 0.f;
        #pragma unroll
        for (int k = 0; k < KERN; k++)
            acc += attn[k] * prot[(size_t)(top + k) * D + t];
        wrow[t] = acc;
    }
    __syncthreads();

    // top_score[d] = sum_r react_part[r][d] + 64*bs[d] + bp[d] + wrow @ Wp[:,d]
    {
        int c    = t & (DP - 1);
        int half = t >> 7;
        int j0   = half * (D / 2);
        float acc = 0.f;
        #pragma unroll 32
        for (int j = 0; j < D / 2; j++)
            acc += wrow[j0 + j] * Wp[(j0 + j) * DP + c];
        if (half) tpart[c] = acc;
        __syncthreads();
        if (!half) {
            float rp = 0.f;
            #pragma unroll
            for (int r = 0; r < N_RPART; r++) rp += d_react_part[r * DP + c];
            ts[c] = acc + tpart[c] + rp + (float)N_INT * bs[c] + bp[c];
        }
    }
    __syncthreads();

    // deltas: prot_out / sub_out are (128, 256) row-major
    {
        float dp_ = 0.f, ds_ = 0.f;
        #pragma unroll 32
        for (int d = 0; d < DP; d++) {
            float s = ts[d];
            dp_ += s * prot_out[d * D + t];
            ds_ += s * sub_out[d * D + t];
        }
        dprot[t] = dp_;
        dsub[t]  = ds_;
    }
    __syncthreads();

    // patch 16 prot rows (out already holds the copy)
    #pragma unroll
    for (int k = 0; k < KERN; k++)
        out[(size_t)(top + k) * D + t] += dprot[t];

    // patch 64 sub rows (set semantics; duplicates write identical value)
    #pragma unroll 4
    for (int m = 0; m < N_INT; m++) {
        int r = idx[m];
        out[(size_t)(N_PROT + r) * D + t] = subn[(size_t)r * D + t] + dsub[t];
    }
}

// ============================================================
extern "C" void kernel_launch(void* const* d_in, const int* in_sizes, int n_in,
                              void* d_out, int out_size)
{
    const float* prot_node = (const float*)d_in[0];
    const float* sub_node  = (const float*)d_in[1];
    const int*   int_index = (const int*)  d_in[2];
    const float* Wp        = (const float*)d_in[3];
    const float* bp        = (const float*)d_in[4];
    const float* Ws        = (const float*)d_in[5];
    const float* bs        = (const float*)d_in[6];
    const float* wa        = (const float*)d_in[7];
    const float* sub_out   = (const float*)d_in[9];
    const float* prot_out  = (const float*)d_in[10];
    float*       out       = (float*)d_out;

    k1_main<<<NB_K1, 256>>>(prot_node, sub_node, int_index, Wp, Ws, wa, out);
    k2_window_final<<<NB_WIN, 256>>>(prot_node, sub_node, int_index, Wp, bp, bs,
                                     sub_out, prot_out, out);
}

// round 6
// speedup vs baseline: 2.5341x; 1.1651x over previous
#include <cuda_runtime.h>
#include <float.h>
#include <math.h>

#define N_PROT 50000
#define N_SUB  2000
#define D      256     // D_PROT == D_SUB
#define DP     128     // D_PROJ
#define KERN   16
#define N_INT  64
#define NW     (N_PROT - KERN + 1)   // 49985

#define NBLK    296       // 2 * 148 SMs — all resident (launch_bounds(256,2))
#define PCHUNK  3125      // prot chunks of 16 rows
#define SCHUNK  125       // sub  chunks of 16 rows
#define TCHUNK  (PCHUNK + SCHUNK + 1)
#define NB_WIN  196       // 196*256 = 50176 >= NW
#define N_RPART 8

// -------- device scratch (no allocations allowed) --------
__device__ float d_g[N_PROT];
__device__ float d_s[N_PROT];
__device__ float d_v[D];          // Wp @ w1
__device__ float d_u[D];          // Wp @ ones
__device__ float d_react_part[N_RPART * DP];
__device__ float d_blkVal[NB_WIN];
__device__ int   d_blkIdx[NB_WIN];
__device__ int   d_count;         // ticket;   reset by finalize
__device__ int   d_vu_done;       // v/u flag; reset by finalize
__device__ int   d_bar;           // barrier;  reset by finalize

__device__ __forceinline__ float dot4(float4 a, float4 b) {
    return a.x*b.x + a.y*b.y + a.z*b.z + a.w*b.w;
}

__global__ void __launch_bounds__(256, 2)
mega(const float* __restrict__ prot,
     const float* __restrict__ subn,
     const int*   __restrict__ idx,
     const float* __restrict__ Wp,
     const float* __restrict__ bp,
     const float* __restrict__ Ws,
     const float* __restrict__ bs,
     const float* __restrict__ wa,
     const float* __restrict__ sub_out,
     const float* __restrict__ prot_out,
     float* __restrict__ out)
{
    __shared__ float sacc[8][32];
    __shared__ float ssumL[32];
    __shared__ float sg[256 + KERN];
    __shared__ float ss[256 + KERN];
    __shared__ float bval[256];
    __shared__ int   bidx[256];
    __shared__ int   s_last, s_top;
    __shared__ float attn[KERN];
    __shared__ float wrow[D];
    __shared__ float ts[DP];
    __shared__ float tpart[DP];
    __shared__ float dprot[D];
    __shared__ float dsub[D];

    int b    = blockIdx.x;
    int t    = threadIdx.x;
    int warp = t >> 5;
    int lane = t & 31;

    // ---------------- producer prologue ----------------
    if (b < 32) {
        // v/u: one warp per Wp row, single coalesced float4 load
        int row = b * 8 + warp;
        float4 w = ((const float4*)(Wp + (size_t)row * DP))[lane];
        float4 a = ((const float4*)wa)[lane];
        float vv = dot4(w, a);
        float uu = w.x + w.y + w.z + w.w;
        #pragma unroll
        for (int o = 16; o > 0; o >>= 1) {
            vv += __shfl_xor_sync(0xffffffffu, vv, o);
            uu += __shfl_xor_sync(0xffffffffu, uu, o);
        }
        if (lane == 0) { d_v[row] = vv; d_u[row] = uu; }
        __syncthreads();
        if (t == 0) { __threadfence(); atomicAdd(&d_vu_done, 1); }
    } else if (b < 32 + N_RPART) {
        // reaction partial over j-slice [j0, j0+32)
        int r  = b - 32;
        int j0 = r * 32;
        int col  = t & 31;
        int row8 = t >> 5;
        float acc = 0.f;
        #pragma unroll
        for (int p = 0; p < 8; p++)
            acc += subn[(size_t)idx[p * 8 + row8] * D + j0 + col];
        sacc[row8][col] = acc;
        __syncthreads();
        if (t < 32) {
            float s = 0.f;
            #pragma unroll
            for (int r8 = 0; r8 < 8; r8++) s += sacc[r8][t];
            ssumL[t] = s;
        }
        __syncthreads();
        if (t < DP) {
            float p = 0.f;
            #pragma unroll
            for (int j = 0; j < 32; j++)
                p += ssumL[j] * Ws[(j0 + j) * DP + t];
            d_react_part[r * DP + t] = p;
        }
    }

    // ---------------- phase A: copy + g/s matvec ----------------
    bool ready = false;
    float4 va, vc, ua, uc;

    for (int chunk = b; chunk < TCHUNK; chunk += NBLK) {
        if (chunk < PCHUNK) {
            int row = chunk * 16 + warp * 2;
            const float4* src = (const float4*)(prot + (size_t)row * D);
            float4*       dst = (float4*)(out + (size_t)row * D);

            float4 a0 = __ldcs(src + lane);
            float4 c0 = __ldcs(src + lane + 32);
            float4 a1 = __ldcs(src + 64 + lane);
            float4 c1 = __ldcs(src + 64 + lane + 32);
            __stcs(dst + lane,           a0);
            __stcs(dst + lane + 32,      c0);
            __stcs(dst + 64 + lane,      a1);
            __stcs(dst + 64 + lane + 32, c1);

            if (!ready) {
                if (t == 0)
                    while (((volatile int*)&d_vu_done)[0] < 32) __nanosleep(64);
                __syncthreads();
                va = ((const float4*)d_v)[lane];
                vc = ((const float4*)d_v)[lane + 32];
                ua = ((const float4*)d_u)[lane];
                uc = ((const float4*)d_u)[lane + 32];
                ready = true;
            }

            float g0 = dot4(a0, va) + dot4(c0, vc);
            float s0 = dot4(a0, ua) + dot4(c0, uc);
            float g1 = dot4(a1, va) + dot4(c1, vc);
            float s1 = dot4(a1, ua) + dot4(c1, uc);
            #pragma unroll
            for (int o = 16; o > 0; o >>= 1) {
                g0 += __shfl_down_sync(0xffffffffu, g0, o);
                s0 += __shfl_down_sync(0xffffffffu, s0, o);
                g1 += __shfl_down_sync(0xffffffffu, g1, o);
                s1 += __shfl_down_sync(0xffffffffu, s1, o);
            }
            if (lane == 0) {
                d_g[row]     = g0;  d_s[row]     = s0;
                d_g[row + 1] = g1;  d_s[row + 1] = s1;
            }
        } else if (chunk < PCHUNK + SCHUNK) {
            int row = (chunk - PCHUNK) * 16 + warp * 2;
            const float4* src = (const float4*)(subn + (size_t)row * D);
            float4*       dst = (float4*)(out + (size_t)(N_PROT + row) * D);
            __stcs(dst + lane,           __ldcs(src + lane));
            __stcs(dst + lane + 32,      __ldcs(src + lane + 32));
            __stcs(dst + 64 + lane,      __ldcs(src + 64 + lane));
            __stcs(dst + 64 + lane + 32, __ldcs(src + 64 + lane + 32));
        } else {
            if (t < N_INT)
                out[(size_t)(N_PROT + N_SUB) * D + t] = (float)idx[t];
        }
    }

    // ---------------- grid barrier ----------------
    __syncthreads();
    if (t == 0) {
        __threadfence();
        atomicAdd(&d_bar, 1);
        while (((volatile int*)&d_bar)[0] < NBLK) __nanosleep(64);
        __threadfence();
    }
    __syncthreads();

    // ---------------- phase B: windows + block argmax ----------------
    if (b < NB_WIN) {
        int base = b * 256;
        for (int i = t; i < 256 + KERN - 1; i += 256) {
            int gi = base + i;
            sg[i] = (gi < N_PROT) ? d_g[gi] : -FLT_MAX;
            ss[i] = (gi < N_PROT) ? d_s[gi] : 0.f;
        }
        __syncthreads();

        int   w = base + t;
        float A = -FLT_MAX;
        if (w < NW) {
            float m = sg[t];
            #pragma unroll
            for (int k = 1; k < KERN; k++) m = fmaxf(m, sg[t + k]);
            float wsum = 0.f, asum = 0.f;
            #pragma unroll
            for (int k = 0; k < KERN; k++) {
                float e = expf(sg[t + k] - m);
                wsum += e;
                asum += e * ss[t + k];
            }
            A = asum / wsum;
        }
        bval[t] = A;
        bidx[t] = w;
        __syncthreads();

        for (int off = 128; off > 0; off >>= 1) {
            if (t < off) {
                float ov = bval[t + off];
                int   oi = bidx[t + off];
                if (ov > bval[t] || (ov == bval[t] && oi < bidx[t])) {
                    bval[t] = ov;
                    bidx[t] = oi;
                }
            }
            __syncthreads();
        }
        if (t == 0) {
            d_blkVal[b] = bval[0];
            d_blkIdx[b] = bidx[0];
        }
    }

    // ---------------- ticket: last block finalizes ----------------
    __syncthreads();
    if (t == 0) {
        __threadfence();
        s_last = (atomicAdd(&d_count, 1) == NBLK - 1);
    }
    __syncthreads();
    if (!s_last) return;

    // reduce 196 candidates -> top
    if (t < NB_WIN) { bval[t] = d_blkVal[t]; bidx[t] = d_blkIdx[t]; }
    else            { bval[t] = -FLT_MAX;    bidx[t] = 0x7fffffff; }
    __syncthreads();
    for (int off = 128; off > 0; off >>= 1) {
        if (t < off) {
            float ov = bval[t + off];
            int   oi = bidx[t + off];
            if (ov > bval[t] || (ov == bval[t] && oi < bidx[t])) {
                bval[t] = ov;
                bidx[t] = oi;
            }
        }
        __syncthreads();
    }
    if (t == 0) {
        s_top = bidx[0];
        d_count = 0; d_vu_done = 0; d_bar = 0;   // reset for graph replay
    }
    __syncthreads();
    int top = s_top;

    // attn (one warp)
    if (t < 32) {
        float gk = (t < KERN) ? d_g[top + t] : -FLT_MAX;
        float m = gk;
        #pragma unroll
        for (int o = 16; o > 0; o >>= 1)
            m = fmaxf(m, __shfl_xor_sync(0xffffffffu, m, o));
        float e = (t < KERN) ? expf(gk - m) : 0.f;
        float sum = e;
        #pragma unroll
        for (int o = 16; o > 0; o >>= 1)
            sum += __shfl_xor_sync(0xffffffffu, sum, o);
        if (t < KERN) attn[t] = e / sum;
    }
    __syncthreads();

    // weighted prot row
    {
        float acc = 0.f;
        #pragma unroll
        for (int k = 0; k < KERN; k++)
            acc += attn[k] * prot[(size_t)(top + k) * D + t];
        wrow[t] = acc;
    }
    __syncthreads();

    // top_score[d] = sum_r react_part[r][d] + 64*bs[d] + bp[d] + wrow @ Wp[:,d]
    {
        int c    = t & (DP - 1);
        int half = t >> 7;
        int j0   = half * (D / 2);
        float acc = 0.f;
        #pragma unroll 32
        for (int j = 0; j < D / 2; j++)
            acc += wrow[j0 + j] * Wp[(j0 + j) * DP + c];
        if (half) tpart[c] = acc;
        __syncthreads();
        if (!half) {
            float rp = 0.f;
            #pragma unroll
            for (int r = 0; r < N_RPART; r++) rp += d_react_part[r * DP + c];
            ts[c] = acc + tpart[c] + rp + (float)N_INT * bs[c] + bp[c];
        }
    }
    __syncthreads();

    // deltas
    {
        float dp_ = 0.f, ds_ = 0.f;
        #pragma unroll 32
        for (int d = 0; d < DP; d++) {
            float s = ts[d];
            dp_ += s * prot_out[d * D + t];
            ds_ += s * sub_out[d * D + t];
        }
        dprot[t] = dp_;
        dsub[t]  = ds_;
    }
    __syncthreads();

    // patch 16 prot rows
    #pragma unroll
    for (int k = 0; k < KERN; k++)
        out[(size_t)(top + k) * D + t] += dprot[t];

    // patch 64 sub rows (set semantics; duplicates identical)
    #pragma unroll 4
    for (int m = 0; m < N_INT; m++) {
        int r = idx[m];
        out[(size_t)(N_PROT + r) * D + t] = subn[(size_t)r * D + t] + dsub[t];
    }
}

// ============================================================
extern "C" void kernel_launch(void* const* d_in, const int* in_sizes, int n_in,
                              void* d_out, int out_size)
{
    const float* prot_node = (const float*)d_in[0];
    const float* sub_node  = (const float*)d_in[1];
    const int*   int_index = (const int*)  d_in[2];
    const float* Wp        = (const float*)d_in[3];
    const float* bp        = (const float*)d_in[4];
    const float* Ws        = (const float*)d_in[5];
    const float* bs        = (const float*)d_in[6];
    const float* wa        = (const float*)d_in[7];
    const float* sub_out   = (const float*)d_in[9];
    const float* prot_out  = (const float*)d_in[10];
    float*       out       = (float*)d_out;

    mega<<<NBLK, 256>>>(prot_node, sub_node, int_index, Wp, bp, Ws, bs, wa,
                        sub_out, prot_out, out);
}

// round 7
// speedup vs baseline: 2.5719x; 1.0149x over previous
#include <cuda_runtime.h>
#include <float.h>
#include <math.h>

#define N_PROT 50000
#define N_SUB  2000
#define D      256     // D_PROT == D_SUB
#define DP     128     // D_PROJ
#define KERN   16
#define N_INT  64
#define NW     (N_PROT - KERN + 1)   // 49985

#define NBLK    444       // 3 * 148 SMs — all resident (launch_bounds(256,3))
#define PCHUNK  3125      // prot chunks of 16 rows
#define SCHUNK  125       // sub  chunks of 16 rows
#define TCHUNK  (PCHUNK + SCHUNK + 1)
#define NB_WIN  196       // 196*256 = 50176 >= NW
#define N_RPART 8

// -------- device scratch (no allocations allowed) --------
__device__ float d_g[N_PROT];
__device__ float d_s[N_PROT];
__device__ float d_v[D];          // Wp @ w1
__device__ float d_u[D];          // Wp @ ones
__device__ float d_react_part[N_RPART * DP];
__device__ float d_blkVal[NB_WIN];
__device__ int   d_blkIdx[NB_WIN];
__device__ int   d_count;         // ticket;   reset by finalize
__device__ int   d_vu_done;       // v/u flag; reset by finalize
__device__ int   d_bar;           // barrier;  reset by finalize

__device__ __forceinline__ float dot4(float4 a, float4 b) {
    return a.x*b.x + a.y*b.y + a.z*b.z + a.w*b.w;
}

__global__ void __launch_bounds__(256, 3)
mega(const float* __restrict__ prot,
     const float* __restrict__ subn,
     const int*   __restrict__ idx,
     const float* __restrict__ Wp,
     const float* __restrict__ bp,
     const float* __restrict__ Ws,
     const float* __restrict__ bs,
     const float* __restrict__ wa,
     const float* __restrict__ sub_out,
     const float* __restrict__ prot_out,
     float* __restrict__ out)
{
    __shared__ float sacc[8][32];
    __shared__ float ssumL[32];
    __shared__ float sg[256 + KERN];
    __shared__ float ss[256 + KERN];
    __shared__ float bval[256];
    __shared__ int   bidx[256];
    __shared__ int   s_last, s_top;
    __shared__ float attn[KERN];
    __shared__ float wrow[D];
    __shared__ float ts[DP];
    __shared__ float tpart[DP];
    __shared__ float dprot[D];
    __shared__ float dsub[D];

    int b    = blockIdx.x;
    int t    = threadIdx.x;
    int warp = t >> 5;
    int lane = t & 31;

    // ---------------- producer prologue ----------------
    if (b < 32) {
        // v/u: one warp per Wp row, single coalesced float4 load
        int row = b * 8 + warp;
        float4 w = ((const float4*)(Wp + (size_t)row * DP))[lane];
        float4 a = ((const float4*)wa)[lane];
        float vv = dot4(w, a);
        float uu = w.x + w.y + w.z + w.w;
        #pragma unroll
        for (int o = 16; o > 0; o >>= 1) {
            vv += __shfl_xor_sync(0xffffffffu, vv, o);
            uu += __shfl_xor_sync(0xffffffffu, uu, o);
        }
        if (lane == 0) { d_v[row] = vv; d_u[row] = uu; }
        __syncthreads();
        if (t == 0) { __threadfence(); atomicAdd(&d_vu_done, 1); }
    } else if (b < 32 + N_RPART) {
        // reaction partial over j-slice [j0, j0+32)
        int r  = b - 32;
        int j0 = r * 32;
        int col  = t & 31;
        int row8 = t >> 5;
        float acc = 0.f;
        #pragma unroll
        for (int p = 0; p < 8; p++)
            acc += subn[(size_t)idx[p * 8 + row8] * D + j0 + col];
        sacc[row8][col] = acc;
        __syncthreads();
        if (t < 32) {
            float s = 0.f;
            #pragma unroll
            for (int r8 = 0; r8 < 8; r8++) s += sacc[r8][t];
            ssumL[t] = s;
        }
        __syncthreads();
        if (t < DP) {
            float p = 0.f;
            #pragma unroll
            for (int j = 0; j < 32; j++)
                p += ssumL[j] * Ws[(j0 + j) * DP + t];
            d_react_part[r * DP + t] = p;
        }
    }

    // ---------------- phase A: prot copy + g/s matvec (pipelined) ----------------
    {
        int chunk = b;
        if (chunk < PCHUNK) {
            float4 va, vc, ua, uc;
            bool ready = false;

            const float4* src = (const float4*)(prot + (size_t)(chunk * 16 + warp * 2) * D);
            float4 a0 = __ldcs(src + lane);
            float4 c0 = __ldcs(src + lane + 32);
            float4 a1 = __ldcs(src + 64 + lane);
            float4 c1 = __ldcs(src + 64 + lane + 32);

            while (true) {
                int nxt = chunk + NBLK;
                bool hn = nxt < PCHUNK;
                float4 n0, n1, n2, n3;
                if (hn) {
                    const float4* nsrc = (const float4*)(prot + (size_t)(nxt * 16 + warp * 2) * D);
                    n0 = __ldcs(nsrc + lane);
                    n1 = __ldcs(nsrc + lane + 32);
                    n2 = __ldcs(nsrc + 64 + lane);
                    n3 = __ldcs(nsrc + 64 + lane + 32);
                }

                int row = chunk * 16 + warp * 2;
                float4* dst = (float4*)(out + (size_t)row * D);
                __stcs(dst + lane,           a0);
                __stcs(dst + lane + 32,      c0);
                __stcs(dst + 64 + lane,      a1);
                __stcs(dst + 64 + lane + 32, c1);

                if (!ready) {
                    if (t == 0)
                        while (((volatile int*)&d_vu_done)[0] < 32) __nanosleep(64);
                    __syncthreads();
                    va = ((const float4*)d_v)[lane];
                    vc = ((const float4*)d_v)[lane + 32];
                    ua = ((const float4*)d_u)[lane];
                    uc = ((const float4*)d_u)[lane + 32];
                    ready = true;
                }

                float g0 = dot4(a0, va) + dot4(c0, vc);
                float s0 = dot4(a0, ua) + dot4(c0, uc);
                float g1 = dot4(a1, va) + dot4(c1, vc);
                float s1 = dot4(a1, ua) + dot4(c1, uc);
                #pragma unroll
                for (int o = 16; o > 0; o >>= 1) {
                    g0 += __shfl_down_sync(0xffffffffu, g0, o);
                    s0 += __shfl_down_sync(0xffffffffu, s0, o);
                    g1 += __shfl_down_sync(0xffffffffu, g1, o);
                    s1 += __shfl_down_sync(0xffffffffu, s1, o);
                }
                if (lane == 0) {
                    d_g[row]     = g0;  d_s[row]     = s0;
                    d_g[row + 1] = g1;  d_s[row + 1] = s1;
                }

                if (!hn) break;
                a0 = n0; c0 = n1; a1 = n2; c1 = n3;
                chunk = nxt;
            }
        }
    }

    // ---------------- phase A': sub copy + idx tail ----------------
    for (int chunk = b; chunk < TCHUNK; chunk += NBLK) {
        if (chunk >= PCHUNK && chunk < PCHUNK + SCHUNK) {
            int row = (chunk - PCHUNK) * 16 + warp * 2;
            const float4* src = (const float4*)(subn + (size_t)row * D);
            float4*       dst = (float4*)(out + (size_t)(N_PROT + row) * D);
            __stcs(dst + lane,           __ldcs(src + lane));
            __stcs(dst + lane + 32,      __ldcs(src + lane + 32));
            __stcs(dst + 64 + lane,      __ldcs(src + 64 + lane));
            __stcs(dst + 64 + lane + 32, __ldcs(src + 64 + lane + 32));
        } else if (chunk == PCHUNK + SCHUNK) {
            if (t < N_INT)
                out[(size_t)(N_PROT + N_SUB) * D + t] = (float)idx[t];
        }
    }

    // ---------------- grid barrier ----------------
    __syncthreads();
    if (t == 0) {
        __threadfence();
        atomicAdd(&d_bar, 1);
        while (((volatile int*)&d_bar)[0] < NBLK) __nanosleep(64);
        __threadfence();
    }
    __syncthreads();

    // ---------------- phase B: windows + block argmax ----------------
    if (b < NB_WIN) {
        int base = b * 256;
        for (int i = t; i < 256 + KERN - 1; i += 256) {
            int gi = base + i;
            sg[i] = (gi < N_PROT) ? d_g[gi] : -FLT_MAX;
            ss[i] = (gi < N_PROT) ? d_s[gi] : 0.f;
        }
        __syncthreads();

        int   w = base + t;
        float A = -FLT_MAX;
        if (w < NW) {
            float m = sg[t];
            #pragma unroll
            for (int k = 1; k < KERN; k++) m = fmaxf(m, sg[t + k]);
            float wsum = 0.f, asum = 0.f;
            #pragma unroll
            for (int k = 0; k < KERN; k++) {
                float e = expf(sg[t + k] - m);
                wsum += e;
                asum += e * ss[t + k];
            }
            A = asum / wsum;
        }
        bval[t] = A;
        bidx[t] = w;
        __syncthreads();

        for (int off = 128; off > 0; off >>= 1) {
            if (t < off) {
                float ov = bval[t + off];
                int   oi = bidx[t + off];
                if (ov > bval[t] || (ov == bval[t] && oi < bidx[t])) {
                    bval[t] = ov;
                    bidx[t] = oi;
                }
            }
            __syncthreads();
        }
        if (t == 0) {
            d_blkVal[b] = bval[0];
            d_blkIdx[b] = bidx[0];
        }
    }

    // ---------------- ticket: last block finalizes ----------------
    __syncthreads();
    if (t == 0) {
        __threadfence();
        s_last = (atomicAdd(&d_count, 1) == NBLK - 1);
    }
    __syncthreads();
    if (!s_last) return;

    // reduce 196 candidates -> top
    if (t < NB_WIN) { bval[t] = d_blkVal[t]; bidx[t] = d_blkIdx[t]; }
    else            { bval[t] = -FLT_MAX;    bidx[t] = 0x7fffffff; }
    __syncthreads();
    for (int off = 128; off > 0; off >>= 1) {
        if (t < off) {
            float ov = bval[t + off];
            int   oi = bidx[t + off];
            if (ov > bval[t] || (ov == bval[t] && oi < bidx[t])) {
                bval[t] = ov;
                bidx[t] = oi;
            }
        }
        __syncthreads();
    }
    if (t == 0) {
        s_top = bidx[0];
        d_count = 0; d_vu_done = 0; d_bar = 0;   // reset for graph replay
    }
    __syncthreads();
    int top = s_top;

    // attn (one warp)
    if (t < 32) {
        float gk = (t < KERN) ? d_g[top + t] : -FLT_MAX;
        float m = gk;
        #pragma unroll
        for (int o = 16; o > 0; o >>= 1)
            m = fmaxf(m, __shfl_xor_sync(0xffffffffu, m, o));
        float e = (t < KERN) ? expf(gk - m) : 0.f;
        float sum = e;
        #pragma unroll
        for (int o = 16; o > 0; o >>= 1)
            sum += __shfl_xor_sync(0xffffffffu, sum, o);
        if (t < KERN) attn[t] = e / sum;
    }
    __syncthreads();

    // weighted prot row
    {
        float acc = 0.f;
        #pragma unroll
        for (int k = 0; k < KERN; k++)
            acc += attn[k] * prot[(size_t)(top + k) * D + t];
        wrow[t] = acc;
    }
    __syncthreads();

    // top_score[d] = sum_r react_part[r][d] + 64*bs[d] + bp[d] + wrow @ Wp[:,d]
    {
        int c    = t & (DP - 1);
        int half = t >> 7;
        int j0   = half * (D / 2);
        float acc = 0.f;
        #pragma unroll 32
        for (int j = 0; j < D / 2; j++)
            acc += wrow[j0 + j] * Wp[(j0 + j) * DP + c];
        if (half) tpart[c] = acc;
        __syncthreads();
        if (!half) {
            float rp = 0.f;
            #pragma unroll
            for (int r = 0; r < N_RPART; r++) rp += d_react_part[r * DP + c];
            ts[c] = acc + tpart[c] + rp + (float)N_INT * bs[c] + bp[c];
        }
    }
    __syncthreads();

    // deltas
    {
        float dp_ = 0.f, ds_ = 0.f;
        #pragma unroll 32
        for (int d = 0; d < DP; d++) {
            float s = ts[d];
            dp_ += s * prot_out[d * D + t];
            ds_ += s * sub_out[d * D + t];
        }
        dprot[t] = dp_;
        dsub[t]  = ds_;
    }
    __syncthreads();

    // patch 16 prot rows
    #pragma unroll
    for (int k = 0; k < KERN; k++)
        out[(size_t)(top + k) * D + t] += dprot[t];

    // patch 64 sub rows (set semantics; duplicates identical)
    #pragma unroll 4
    for (int m = 0; m < N_INT; m++) {
        int r = idx[m];
        out[(size_t)(N_PROT + r) * D + t] = subn[(size_t)r * D + t] + dsub[t];
    }
}

// ============================================================
extern "C" void kernel_launch(void* const* d_in, const int* in_sizes, int n_in,
                              void* d_out, int out_size)
{
    const float* prot_node = (const float*)d_in[0];
    const float* sub_node  = (const float*)d_in[1];
    const int*   int_index = (const int*)  d_in[2];
    const float* Wp        = (const float*)d_in[3];
    const float* bp        = (const float*)d_in[4];
    const float* Ws        = (const float*)d_in[5];
    const float* bs        = (const float*)d_in[6];
    const float* wa        = (const float*)d_in[7];
    const float* sub_out   = (const float*)d_in[9];
    const float* prot_out  = (const float*)d_in[10];
    float*       out       = (float*)d_out;

    mega<<<NBLK, 256>>>(prot_node, sub_node, int_index, Wp, bp, Ws, bs, wa,
                        sub_out, prot_out, out);
}